// round 15
// baseline (speedup 1.0000x reference)
#include <cuda_runtime.h>
#include <cuda_bf16.h>
#include <math_constants.h>

// Problem constants
#define BB   2
#define LL   2048
#define CC   512
#define HH   8
#define DD   64
#define MM   (BB*LL)          // 4096 rows
#define NQKV (3*CC)           // 1536
#define NQ   16               // L/128 (mask Q-block granularity)
#define NK   32               // L/64
#define SCALE 0.125f          // D^-0.5
#define SIMTH 0.6f
#define CDFTH 0.98f

// Scratch (allocation-free rule -> device globals)
__device__ float g_q[BB*HH*LL*DD];        // raw [B,H,L,D] (meansim)
__device__ float g_k[BB*HH*LL*DD];        // raw [B,H,L,D] (meansim)
__device__ float g_qp[BB*HH*NQ*8192];     // Q A-fragments, tf32(q*SCALE)
__device__ float g_kp[BB*HH*NK*4096];     // K paired B-frags [kk][ntp][lane][4]
__device__ float g_vp[BB*HH*NK*4096];     // V paired B-frags [kk][ntp][lane][4]
__device__ float g_o[BB*LL*CC];           // [B,L,C]
__device__ int   g_mask[BB*HH*NQ*NK];     // 1 = keep block
__device__ float g_qm[BB*HH][NQ][DD];
__device__ float g_km[BB*HH][NK][DD];
__device__ float g_qsim[BB*HH][NQ];
__device__ float g_ksim[BB*HH][NK];

__device__ __forceinline__ unsigned f2tf32(float x) {
    unsigned r;
    asm("cvt.rna.tf32.f32 %0, %1;" : "=r"(r) : "f"(x));
    return r;
}
__device__ __forceinline__ float tf32f(float x) {
    return __uint_as_float(f2tf32(x));
}

__device__ __forceinline__ void mma_tf32(float c[4],
                                         unsigned a0, unsigned a1, unsigned a2, unsigned a3,
                                         unsigned b0, unsigned b1) {
    asm volatile(
        "mma.sync.aligned.m16n8k8.row.col.f32.tf32.tf32.f32 "
        "{%0,%1,%2,%3}, {%4,%5,%6,%7}, {%8,%9}, {%0,%1,%2,%3};"
        : "+f"(c[0]), "+f"(c[1]), "+f"(c[2]), "+f"(c[3])
        : "r"(a0), "r"(a1), "r"(a2), "r"(a3), "r"(b0), "r"(b1));
}

__device__ __forceinline__ void cp16(unsigned smem_dst, const void* gsrc) {
    asm volatile("cp.async.ca.shared.global [%0], [%1], 16;"
                 :: "r"(smem_dst), "l"(gsrc));
}

__device__ __forceinline__ void atomicMinFloat(float* addr, float val) {
    int* ia = (int*)addr;
    int old = *ia;
    while (__int_as_float(old) > val) {
        int assumed = old;
        old = atomicCAS(ia, assumed, __float_as_int(val));
        if (old == assumed) break;
    }
}

// ---------------------------------------------------------------------------
// tf32 tensor-core GEMM: C[M,N] = A[M,K=512] @ B[K,N] + bias
// 128x128 tile, 256 threads = 8 warps (4M x 2N), warp tile 32x64,
// cp.async double-buffered.  SCATTER=true: writes raw q/k + packed qp/kp/vp.
// ---------------------------------------------------------------------------
#define GA_ST 36
#define GB_ST 136
#define GA_FL (128*GA_ST)          // 4608
#define GB_FL (32*GB_ST)           // 4352
#define GEMM_SMEM_FLOATS (2*GA_FL + 2*GB_FL)
#define GEMM_SMEM_BYTES  (GEMM_SMEM_FLOATS*4)   // 71680

extern __shared__ float sm_dyn[];

template<int N, bool SCATTER>
__global__ void __launch_bounds__(256) gemm_tf32(const float* __restrict__ A,
                                                 const float* __restrict__ Bw,
                                                 const float* __restrict__ bias,
                                                 float* __restrict__ out) {
    const int K = CC;
    const float* Ap = SCATTER ? A : (const float*)g_o;
    int m0 = blockIdx.y * 128, n0 = blockIdx.x * 128;
    float* Asm = sm_dyn;
    float* Bsm = sm_dyn + 2 * GA_FL;
    unsigned sbase = (unsigned)__cvta_generic_to_shared(sm_dyn);
    int tid = threadIdx.x;
    int wid = tid >> 5, lane = tid & 31;
    int lr = lane >> 2, lc = lane & 3;
    int warp_m = wid & 3, warp_n = wid >> 2;

    float c[2][8][4] = {};

    auto stage = [&](int buf, int k0) {
        unsigned a_s = sbase + (unsigned)(buf * GA_FL) * 4u;
        unsigned b_s = sbase + (unsigned)(2 * GA_FL + buf * GB_FL) * 4u;
        #pragma unroll
        for (int i = 0; i < 4; i++) {
            int f4 = tid + i * 256;              // 1024 f4 of A (128x32)
            int r = f4 >> 3, cg = f4 & 7;
            cp16(a_s + (unsigned)(r * GA_ST + cg * 4) * 4u,
                 &Ap[(size_t)(m0 + r) * K + k0 + cg * 4]);
        }
        #pragma unroll
        for (int i = 0; i < 4; i++) {
            int f4 = tid + i * 256;              // 1024 f4 of B (32x128)
            int r = f4 >> 5, cg = f4 & 31;
            cp16(b_s + (unsigned)(r * GB_ST + cg * 4) * 4u,
                 &Bw[(size_t)(k0 + r) * N + n0 + cg * 4]);
        }
        asm volatile("cp.async.commit_group;");
    };

    stage(0, 0);
    const int NCHUNK = K / 32;
    for (int ch = 0; ch < NCHUNK; ch++) {
        int buf = ch & 1;
        if (ch < NCHUNK - 1) {
            stage(buf ^ 1, (ch + 1) * 32);
            asm volatile("cp.async.wait_group 1;");
        } else {
            asm volatile("cp.async.wait_group 0;");
        }
        __syncthreads();

        const float* Aw = Asm + buf * GA_FL + (warp_m * 32) * GA_ST;
        const float* Bb = Bsm + buf * GB_FL;
        #pragma unroll
        for (int kk = 0; kk < 4; kk++) {
            int kf = kk * 8;
            unsigned a[2][4];
            #pragma unroll
            for (int mt = 0; mt < 2; mt++) {
                a[mt][0] = f2tf32(Aw[(mt * 16 + lr    ) * GA_ST + kf + lc    ]);
                a[mt][1] = f2tf32(Aw[(mt * 16 + lr + 8) * GA_ST + kf + lc    ]);
                a[mt][2] = f2tf32(Aw[(mt * 16 + lr    ) * GA_ST + kf + lc + 4]);
                a[mt][3] = f2tf32(Aw[(mt * 16 + lr + 8) * GA_ST + kf + lc + 4]);
            }
            unsigned bf[8][2];
            #pragma unroll
            for (int nt = 0; nt < 8; nt++) {
                int nn = warp_n * 64 + nt * 8 + lr;
                bf[nt][0] = f2tf32(Bb[(kf + lc    ) * GB_ST + nn]);
                bf[nt][1] = f2tf32(Bb[(kf + lc + 4) * GB_ST + nn]);
            }
            #pragma unroll
            for (int mt = 0; mt < 2; mt++)
                #pragma unroll
                for (int nt = 0; nt < 8; nt++)
                    mma_tf32(c[mt][nt], a[mt][0], a[mt][1], a[mt][2], a[mt][3],
                             bf[nt][0], bf[nt][1]);
        }
        __syncthreads();
    }

    // Epilogue
    int t = n0 >> 9;   // uniform per CTA when SCATTER
    #pragma unroll
    for (int mt = 0; mt < 2; mt++) {
        #pragma unroll
        for (int half = 0; half < 2; half++) {
            int row = m0 + warp_m * 32 + mt * 16 + lr + half * 8;
            #pragma unroll
            for (int nt = 0; nt < 8; nt++) {
                int col = n0 + warp_n * 64 + nt * 8 + 2 * lc;
                float v0 = c[mt][nt][half * 2 + 0] + bias[col];
                float v1 = c[mt][nt][half * 2 + 1] + bias[col + 1];
                if (SCATTER) {
                    int b = row >> 11, l = row & 2047;
                    int h = (col & 511) >> 6;
                    int d = col & 63, d1 = d + 1;
                    int bh = b * HH + h;
                    if (t == 0) {
                        *(float2*)&g_q[((size_t)bh * LL + l) * DD + d] =
                            make_float2(v0, v1);
                        int qt = l >> 7, r = l & 127;
                        int w = r >> 4, lr2 = r & 7, hf = (r >> 3) & 1;
                        float* qp = g_qp + ((size_t)(bh * NQ + qt)) * 8192 + w * 1024;
                        qp[(d  >> 3) * 128 + (lr2 * 4 + (d  & 3)) * 4 + hf + 2 * ((d  >> 2) & 1)]
                            = tf32f(v0 * SCALE);
                        qp[(d1 >> 3) * 128 + (lr2 * 4 + (d1 & 3)) * 4 + hf + 2 * ((d1 >> 2) & 1)]
                            = tf32f(v1 * SCALE);
                    } else if (t == 1) {
                        *(float2*)&g_k[((size_t)bh * LL + l) * DD + d] =
                            make_float2(v0, v1);
                        // paired-fragment layout [kk][ntp][lane][4]
                        int kb = l >> 6, n = l & 63;
                        int kk = d >> 3, lcc = d & 3, hi = (d >> 2) & 1;
                        int nt2 = n >> 3, lrr = n & 7;
                        float* kp = g_kp + ((size_t)(bh * NK + kb)) * 4096
                                  + kk * 512 + (nt2 >> 1) * 128
                                  + (lrr * 4 + lcc) * 4 + (nt2 & 1) * 2 + hi;
                        kp[0] = tf32f(v0);
                        kp[4] = tf32f(v1);      // d+1 -> lane+1 -> +4 floats
                    } else {
                        int kb = l >> 6, k64 = l & 63;
                        int kk = k64 >> 3, lcv = k64 & 3, hi = (k64 >> 2) & 1;
                        int ntv = d >> 3, lrv = d & 7;
                        float* vp = g_vp + ((size_t)(bh * NK + kb)) * 4096
                                  + kk * 512 + (ntv >> 1) * 128
                                  + (lrv * 4 + lcv) * 4 + (ntv & 1) * 2 + hi;
                        vp[0]  = tf32f(v0);
                        vp[16] = tf32f(v1);     // d+1 -> lrv+1 -> lane+4 -> +16
                    }
                } else {
                    *(float2*)&out[(size_t)row * N + col] = make_float2(v0, v1);
                }
            }
        }
    }
}

// ---------------------------------------------------------------------------
// Kernel 2a: per-block mean + min-cosine.
// ---------------------------------------------------------------------------
__global__ void __launch_bounds__(256) meansim_kernel() {
    int bh = blockIdx.y;
    int j  = blockIdx.x;
    bool isQ = j < NQ;
    int blk  = isQ ? j : j - NQ;
    int rows = isQ ? 128 : 64;
    const float* base = (isQ ? g_q : g_k) + (size_t)bh * LL * DD + (size_t)blk * rows * DD;
    __shared__ float psum[256];
    __shared__ float mean[64];
    __shared__ float nrm;
    __shared__ float simv;
    int tid = threadIdx.x;
    if (tid == 0) simv = 1e30f;

    {
        int d = tid & 63, rg = tid >> 6;
        float acc = 0.f;
        for (int r = rg; r < rows; r += 4) acc += base[r * DD + d];
        psum[tid] = acc;
    }
    __syncthreads();
    if (tid < 64) {
        float m = (psum[tid] + psum[tid + 64] + psum[tid + 128] + psum[tid + 192])
                  * (1.f / rows);
        mean[tid] = m;
        float* gm = isQ ? &g_qm[bh][blk][0] : &g_km[bh][blk][0];
        gm[tid] = m;
    }
    __syncthreads();
    if (tid < 32) {
        float s = mean[tid] * mean[tid] + mean[tid + 32] * mean[tid + 32];
        #pragma unroll
        for (int o = 16; o >= 1; o >>= 1) s += __shfl_xor_sync(0xffffffffu, s, o);
        if (tid == 0) nrm = sqrtf(s);
    }
    __syncthreads();
    float mnorm = nrm;

    float cosv;
    if (isQ) {
        int row = tid >> 1, half = tid & 1;
        const float* p  = base + row * DD + half * 32;
        const float* mp = mean + half * 32;
        float dot = 0.f, nn = 0.f;
        #pragma unroll
        for (int d = 0; d < 32; d++) { float v = p[d]; dot += v * mp[d]; nn += v * v; }
        dot += __shfl_xor_sync(0xffffffffu, dot, 1);
        nn  += __shfl_xor_sync(0xffffffffu, nn,  1);
        cosv = dot / ((sqrtf(nn) + 1e-6f) * (mnorm + 1e-6f));
    } else {
        int row = tid >> 2, qd = tid & 3;
        const float* p  = base + row * DD + qd * 16;
        const float* mp = mean + qd * 16;
        float dot = 0.f, nn = 0.f;
        #pragma unroll
        for (int d = 0; d < 16; d++) { float v = p[d]; dot += v * mp[d]; nn += v * v; }
        dot += __shfl_xor_sync(0xffffffffu, dot, 1);
        dot += __shfl_xor_sync(0xffffffffu, dot, 2);
        nn  += __shfl_xor_sync(0xffffffffu, nn,  1);
        nn  += __shfl_xor_sync(0xffffffffu, nn,  2);
        cosv = dot / ((sqrtf(nn) + 1e-6f) * (mnorm + 1e-6f));
    }
    #pragma unroll
    for (int o = 16; o >= 1; o >>= 1)
        cosv = fminf(cosv, __shfl_xor_sync(0xffffffffu, cosv, o));
    if ((tid & 31) == 0) atomicMinFloat(&simv, cosv);
    __syncthreads();
    if (tid == 0) {
        if (isQ) g_qsim[bh][blk] = simv; else g_ksim[bh][blk] = simv;
    }
}

// ---------------------------------------------------------------------------
// Kernel 2b: pooled softmax + CDF keep -> block mask.
// ---------------------------------------------------------------------------
__global__ void __launch_bounds__(256) mask_kernel() {
    int bh = blockIdx.x;
    __shared__ float pooled[NQ][NK];
    __shared__ float qs[NQ], kss[NK];
    int tid = threadIdx.x;
    if (tid < NQ) qs[tid]  = g_qsim[bh][tid];
    if (tid < NK) kss[tid] = g_ksim[bh][tid];
    for (int e = tid; e < NQ * NK; e += 256) {
        int qi = e >> 5, ki = e & 31;
        const float* a = g_qm[bh][qi];
        const float* b = g_km[bh][ki];
        float dot = 0.f;
        #pragma unroll
        for (int d = 0; d < DD; d++) dot += a[d] * b[d];
        pooled[qi][ki] = dot * SCALE;
    }
    __syncthreads();
    if (tid < NQ) {
        float vals[NK]; int idx[NK];
        float mx = -CUDART_INF_F;
        for (int i = 0; i < NK; i++) mx = fmaxf(mx, pooled[tid][i]);
        float sum = 0.f;
        for (int i = 0; i < NK; i++) { vals[i] = expf(pooled[tid][i] - mx); sum += vals[i]; }
        float inv = 1.f / sum;
        for (int i = 0; i < NK; i++) { vals[i] *= inv; idx[i] = i; }
        for (int i = 1; i < NK; i++) {
            float kv = vals[i]; int ki = idx[i];
            int j = i - 1;
            while (j >= 0 && vals[j] < kv) { vals[j+1] = vals[j]; idx[j+1] = idx[j]; j--; }
            vals[j+1] = kv; idx[j+1] = ki;
        }
        unsigned keep = 0u;
        float csum = 0.f;
        for (int i = 0; i < NK; i++) {
            if (csum < CDFTH) keep |= (1u << idx[i]);
            csum += vals[i];
        }
        bool qself = qs[tid] > SIMTH;
        int* mrow = g_mask + (bh * NQ + tid) * NK;
        for (int ki = 0; ki < NK; ki++) {
            bool kself = kss[ki] > SIMTH;
            mrow[ki] = (((keep >> ki) & 1u) || !qself || !kself) ? 1 : 0;
        }
    }
}

// ---------------------------------------------------------------------------
// Kernel 3: block-sparse flash attention, tf32 mma.
// Q A-frags in registers; K/V B-frags read DIRECTLY from global via
// coalesced LDG.128 (paired-fragment layout: 1 load -> 4 mma).
// No K/V smem, no cp.async, no __syncthreads in the main loop.
// grid = (16 q-tiles of 128 rows, 16 bh), 128 threads = 4 warps.
// smem: Pp[4 w][1024] = 16 KB static.
// ---------------------------------------------------------------------------
__global__ void __launch_bounds__(128, 2) attn_tf32() {
    const int qb = blockIdx.x;
    const int bh = blockIdx.y;
    const int b = bh >> 3, h = bh & 7;
    const int tid  = threadIdx.x;
    const int wid  = tid >> 5;          // 0..3, warp owns rows wid*32..wid*32+31
    const int lane = tid & 31;
    const int lr = lane >> 2;
    const int lc = lane & 3;

    __shared__ float Pp[4][1024];
    __shared__ int s_list[NK];
    __shared__ int s_nk;
    float* PpW = &Pp[wid][0];

    // Q A-fragments -> registers (loop-invariant; coalesced LDG.128)
    unsigned qreg[2][8][4];
    {
        const float* qg = g_qp + ((size_t)(bh * NQ + qb)) * 8192 + (2 * wid) * 1024;
        #pragma unroll
        for (int g = 0; g < 2; g++)
            #pragma unroll
            for (int kk = 0; kk < 8; kk++) {
                float4 v = *(const float4*)(qg + g * 1024 + kk * 128 + lane * 4);
                qreg[g][kk][0] = __float_as_uint(v.x);
                qreg[g][kk][1] = __float_as_uint(v.y);
                qreg[g][kk][2] = __float_as_uint(v.z);
                qreg[g][kk][3] = __float_as_uint(v.w);
            }
    }

    // Kept-block list
    const int* mrow = g_mask + (bh * NQ + qb) * NK;
    if (tid == 0) {
        int c = 0;
        for (int i = 0; i < NK; i++) if (mrow[i]) s_list[c++] = i;
        s_nk = c;
    }
    __syncthreads();
    const int nkeep = s_nk;

    const float* __restrict__ kgp = g_kp + (size_t)bh * NK * 4096;
    const float* __restrict__ vgp = g_vp + (size_t)bh * NK * 4096;

    float o[2][8][4];
    #pragma unroll
    for (int g = 0; g < 2; g++)
        #pragma unroll
        for (int nt = 0; nt < 8; nt++)
            #pragma unroll
            for (int j = 0; j < 4; j++) o[g][nt][j] = 0.f;
    float m[4] = {-CUDART_INF_F, -CUDART_INF_F, -CUDART_INF_F, -CUDART_INF_F};
    float l[4] = {0.f, 0.f, 0.f, 0.f};

    for (int i = 0; i < nkeep; i++) {
        int kb = s_list[i];
        const float4* __restrict__ Kg = (const float4*)(kgp + (size_t)kb * 4096);
        const float4* __restrict__ Vg = (const float4*)(vgp + (size_t)kb * 4096);

        // ---- S = Q K^T : 32 rows x 64 kpos per warp ----
        float sc[2][8][4];
        #pragma unroll
        for (int g = 0; g < 2; g++)
            #pragma unroll
            for (int nt = 0; nt < 8; nt++)
                #pragma unroll
                for (int j = 0; j < 4; j++) sc[g][nt][j] = 0.f;

        #pragma unroll
        for (int kk = 0; kk < 8; kk++) {
            #pragma unroll
            for (int ntp = 0; ntp < 4; ntp++) {
                float4 kv = Kg[kk * 128 + ntp * 32 + lane];
                unsigned b0 = __float_as_uint(kv.x), b1 = __float_as_uint(kv.y);
                unsigned b2 = __float_as_uint(kv.z), b3 = __float_as_uint(kv.w);
                int nte = 2 * ntp, nto = nte + 1;
                mma_tf32(sc[0][nte], qreg[0][kk][0], qreg[0][kk][1],
                         qreg[0][kk][2], qreg[0][kk][3], b0, b1);
                mma_tf32(sc[1][nte], qreg[1][kk][0], qreg[1][kk][1],
                         qreg[1][kk][2], qreg[1][kk][3], b0, b1);
                mma_tf32(sc[0][nto], qreg[0][kk][0], qreg[0][kk][1],
                         qreg[0][kk][2], qreg[0][kk][3], b2, b3);
                mma_tf32(sc[1][nto], qreg[1][kk][0], qreg[1][kk][1],
                         qreg[1][kk][2], qreg[1][kk][3], b2, b3);
            }
        }

        // ---- Online softmax maxes (4 row-groups: lr, lr+8, 16+lr, 24+lr) ----
        float r0 = -CUDART_INF_F, r1 = -CUDART_INF_F;
        float r2 = -CUDART_INF_F, r3 = -CUDART_INF_F;
        #pragma unroll
        for (int nt = 0; nt < 8; nt++) {
            r0 = fmaxf(r0, fmaxf(sc[0][nt][0], sc[0][nt][1]));
            r1 = fmaxf(r1, fmaxf(sc[0][nt][2], sc[0][nt][3]));
            r2 = fmaxf(r2, fmaxf(sc[1][nt][0], sc[1][nt][1]));
            r3 = fmaxf(r3, fmaxf(sc[1][nt][2], sc[1][nt][3]));
        }
        r0 = fmaxf(r0, __shfl_xor_sync(0xffffffffu, r0, 1));
        r0 = fmaxf(r0, __shfl_xor_sync(0xffffffffu, r0, 2));
        r1 = fmaxf(r1, __shfl_xor_sync(0xffffffffu, r1, 1));
        r1 = fmaxf(r1, __shfl_xor_sync(0xffffffffu, r1, 2));
        r2 = fmaxf(r2, __shfl_xor_sync(0xffffffffu, r2, 1));
        r2 = fmaxf(r2, __shfl_xor_sync(0xffffffffu, r2, 2));
        r3 = fmaxf(r3, __shfl_xor_sync(0xffffffffu, r3, 1));
        r3 = fmaxf(r3, __shfl_xor_sync(0xffffffffu, r3, 2));
        float mn0 = fmaxf(m[0], r0), mn1 = fmaxf(m[1], r1);
        float mn2 = fmaxf(m[2], r2), mn3 = fmaxf(m[3], r3);
        float c0 = __expf(m[0] - mn0), c1 = __expf(m[1] - mn1);
        float c2 = __expf(m[2] - mn2), c3 = __expf(m[3] - mn3);
        #pragma unroll
        for (int nt = 0; nt < 8; nt++) {
            o[0][nt][0] *= c0; o[0][nt][1] *= c0;
            o[0][nt][2] *= c1; o[0][nt][3] *= c1;
            o[1][nt][0] *= c2; o[1][nt][1] *= c2;
            o[1][nt][2] *= c3; o[1][nt][3] *= c3;
        }

        // ---- PV in two 4-slice batches (P via per-warp smem) ----
        float s0 = 0.f, s1 = 0.f, s2 = 0.f, s3 = 0.f;
        #pragma unroll
        for (int ph = 0; ph < 2; ph++) {
            int base_nt = ph * 4;
            if (ph) __syncwarp();     // phase-A reads done before overwrite
            #pragma unroll
            for (int j = 0; j < 4; j++) {
                int nt = base_nt + j;
                float p00 = __expf(sc[0][nt][0] - mn0);
                float p01 = __expf(sc[0][nt][1] - mn0);
                float p02 = __expf(sc[0][nt][2] - mn1);
                float p03 = __expf(sc[0][nt][3] - mn1);
                float p10 = __expf(sc[1][nt][0] - mn2);
                float p11 = __expf(sc[1][nt][1] - mn2);
                float p12 = __expf(sc[1][nt][2] - mn3);
                float p13 = __expf(sc[1][nt][3] - mn3);
                s0 += p00 + p01; s1 += p02 + p03;
                s2 += p10 + p11; s3 += p12 + p13;
                float* Pb0 = PpW + j * 256;          // g=0
                float* Pb1 = PpW + j * 256 + 128;    // g=1
                *(float2*)(Pb0 +      lane * 2) = make_float2(tf32f(p00), tf32f(p02));
                *(float2*)(Pb0 + 64 + lane * 2) = make_float2(tf32f(p01), tf32f(p03));
                *(float2*)(Pb1 +      lane * 2) = make_float2(tf32f(p10), tf32f(p12));
                *(float2*)(Pb1 + 64 + lane * 2) = make_float2(tf32f(p11), tf32f(p13));
            }
            __syncwarp();
            #pragma unroll
            for (int j = 0; j < 4; j++) {
                int kk = base_nt + j;
                int poff = (lc & 1) * 64 + (lr * 4 + (lc >> 1)) * 2;
                const float* pb0 = PpW + j * 256 + poff;
                const float* pb1 = pb0 + 128;
                float2 A01 = *(const float2*)pb0;
                float2 A23 = *(const float2*)(pb0 + 4);
                float2 B01 = *(const float2*)pb1;
                float2 B23 = *(const float2*)(pb1 + 4);
                unsigned aA0 = __float_as_uint(A01.x), aA1 = __float_as_uint(A01.y);
                unsigned aA2 = __float_as_uint(A23.x), aA3 = __float_as_uint(A23.y);
                unsigned aB0 = __float_as_uint(B01.x), aB1 = __float_as_uint(B01.y);
                unsigned aB2 = __float_as_uint(B23.x), aB3 = __float_as_uint(B23.y);
                #pragma unroll
                for (int ntp2 = 0; ntp2 < 4; ntp2++) {
                    float4 vv = Vg[kk * 128 + ntp2 * 32 + lane];
                    unsigned b0 = __float_as_uint(vv.x), b1 = __float_as_uint(vv.y);
                    unsigned b2 = __float_as_uint(vv.z), b3 = __float_as_uint(vv.w);
                    int nte = 2 * ntp2, nto = nte + 1;
                    mma_tf32(o[0][nte], aA0, aA1, aA2, aA3, b0, b1);
                    mma_tf32(o[1][nte], aB0, aB1, aB2, aB3, b0, b1);
                    mma_tf32(o[0][nto], aA0, aA1, aA2, aA3, b2, b3);
                    mma_tf32(o[1][nto], aB0, aB1, aB2, aB3, b2, b3);
                }
            }
        }
        s0 += __shfl_xor_sync(0xffffffffu, s0, 1);
        s0 += __shfl_xor_sync(0xffffffffu, s0, 2);
        s1 += __shfl_xor_sync(0xffffffffu, s1, 1);
        s1 += __shfl_xor_sync(0xffffffffu, s1, 2);
        s2 += __shfl_xor_sync(0xffffffffu, s2, 1);
        s2 += __shfl_xor_sync(0xffffffffu, s2, 2);
        s3 += __shfl_xor_sync(0xffffffffu, s3, 1);
        s3 += __shfl_xor_sync(0xffffffffu, s3, 2);
        l[0] = l[0] * c0 + s0;
        l[1] = l[1] * c1 + s1;
        l[2] = l[2] * c2 + s2;
        l[3] = l[3] * c3 + s3;
        m[0] = mn0; m[1] = mn1; m[2] = mn2; m[3] = mn3;
    }

    // Epilogue: normalize and scatter to g_o
    float inv0 = 1.f / l[0], inv1 = 1.f / l[1];
    float inv2 = 1.f / l[2], inv3 = 1.f / l[3];
    int r0r = qb * 128 + wid * 32 + lr;
    float* og = g_o + (size_t)b * LL * CC + h * DD;
    #pragma unroll
    for (int nt = 0; nt < 8; nt++) {
        float2 w0 = make_float2(o[0][nt][0] * inv0, o[0][nt][1] * inv0);
        float2 w1 = make_float2(o[0][nt][2] * inv1, o[0][nt][3] * inv1);
        float2 w2 = make_float2(o[1][nt][0] * inv2, o[1][nt][1] * inv2);
        float2 w3 = make_float2(o[1][nt][2] * inv3, o[1][nt][3] * inv3);
        *(float2*)&og[(size_t)(r0r     ) * CC + nt * 8 + 2 * lc] = w0;
        *(float2*)&og[(size_t)(r0r +  8) * CC + nt * 8 + 2 * lc] = w1;
        *(float2*)&og[(size_t)(r0r + 16) * CC + nt * 8 + 2 * lc] = w2;
        *(float2*)&og[(size_t)(r0r + 24) * CC + nt * 8 + 2 * lc] = w3;
    }
}

// ---------------------------------------------------------------------------
extern "C" void kernel_launch(void* const* d_in, const int* in_sizes, int n_in,
                              void* d_out, int out_size) {
    const float* x     = (const float*)d_in[0];
    const float* Wqkv  = (const float*)d_in[1];
    const float* bqkv  = (const float*)d_in[2];
    const float* Wproj = (const float*)d_in[3];
    const float* bproj = (const float*)d_in[4];
    float* out = (float*)d_out;

    cudaFuncSetAttribute(gemm_tf32<NQKV, true>,
                         cudaFuncAttributeMaxDynamicSharedMemorySize, GEMM_SMEM_BYTES);
    cudaFuncSetAttribute(gemm_tf32<CC, false>,
                         cudaFuncAttributeMaxDynamicSharedMemorySize, GEMM_SMEM_BYTES);

    gemm_tf32<NQKV, true><<<dim3(NQKV / 128, MM / 128), 256, GEMM_SMEM_BYTES>>>(
        x, Wqkv, bqkv, nullptr);
    meansim_kernel<<<dim3(NQ + NK, BB * HH), 256>>>();
    mask_kernel<<<BB * HH, 256>>>();
    attn_tf32<<<dim3(NQ, BB * HH), 128>>>();
    gemm_tf32<CC, false><<<dim3(CC / 128, MM / 128), 256, GEMM_SMEM_BYTES>>>(
        nullptr, Wproj, bproj, out);
}

// round 16
// speedup vs baseline: 1.1051x; 1.1051x over previous
#include <cuda_runtime.h>
#include <cuda_bf16.h>
#include <math_constants.h>

// Problem constants
#define BB   2
#define LL   2048
#define CC   512
#define HH   8
#define DD   64
#define MM   (BB*LL)          // 4096 rows
#define NQKV (3*CC)           // 1536
#define NQ   16               // L/128 (mask Q-block granularity)
#define NK   32               // L/64
#define SCALE 0.125f          // D^-0.5
#define SIMTH 0.6f
#define CDFTH 0.98f

// Scratch (allocation-free rule -> device globals)
__device__ float g_q[BB*HH*LL*DD];        // raw [B,H,L,D] (meansim)
__device__ float g_k[BB*HH*LL*DD];        // raw [B,H,L,D] (meansim)
__device__ float g_qp[BB*HH*NQ*8192];     // Q A-fragments, tf32(q*SCALE)
__device__ float g_kp[BB*HH*NK*4096];     // K paired B-frags [kk][ntp][lane][4]
__device__ float g_vp[BB*HH*NK*4096];     // V paired B-frags [kk][ntp][lane][4]
__device__ float g_o[BB*LL*CC];           // [B,L,C]
__device__ int   g_mask[BB*HH*NQ*NK];     // 1 = keep block
__device__ float g_qm[BB*HH][NQ][DD];
__device__ float g_km[BB*HH][NK][DD];
__device__ float g_qsim[BB*HH][NQ];
__device__ float g_ksim[BB*HH][NK];

__device__ __forceinline__ unsigned f2tf32(float x) {
    unsigned r;
    asm("cvt.rna.tf32.f32 %0, %1;" : "=r"(r) : "f"(x));
    return r;
}
__device__ __forceinline__ float tf32f(float x) {
    return __uint_as_float(f2tf32(x));
}

__device__ __forceinline__ void mma_tf32(float c[4],
                                         unsigned a0, unsigned a1, unsigned a2, unsigned a3,
                                         unsigned b0, unsigned b1) {
    asm volatile(
        "mma.sync.aligned.m16n8k8.row.col.f32.tf32.tf32.f32 "
        "{%0,%1,%2,%3}, {%4,%5,%6,%7}, {%8,%9}, {%0,%1,%2,%3};"
        : "+f"(c[0]), "+f"(c[1]), "+f"(c[2]), "+f"(c[3])
        : "r"(a0), "r"(a1), "r"(a2), "r"(a3), "r"(b0), "r"(b1));
}

__device__ __forceinline__ void cp16(unsigned smem_dst, const void* gsrc) {
    asm volatile("cp.async.ca.shared.global [%0], [%1], 16;"
                 :: "r"(smem_dst), "l"(gsrc));
}

__device__ __forceinline__ void atomicMinFloat(float* addr, float val) {
    int* ia = (int*)addr;
    int old = *ia;
    while (__int_as_float(old) > val) {
        int assumed = old;
        old = atomicCAS(ia, assumed, __float_as_int(val));
        if (old == assumed) break;
    }
}

// ---------------------------------------------------------------------------
// tf32 tensor-core GEMM: C[M,N] = A[M,K=512] @ B[K,N] + bias
// 128x128 tile, 256 threads = 8 warps (4M x 2N), warp tile 32x64,
// cp.async double-buffered.  SCATTER=true: writes raw q/k + packed qp/kp/vp.
// ---------------------------------------------------------------------------
#define GA_ST 36
#define GB_ST 136
#define GA_FL (128*GA_ST)          // 4608
#define GB_FL (32*GB_ST)           // 4352
#define GEMM_SMEM_FLOATS (2*GA_FL + 2*GB_FL)
#define GEMM_SMEM_BYTES  (GEMM_SMEM_FLOATS*4)   // 71680

extern __shared__ float sm_dyn[];

template<int N, bool SCATTER>
__global__ void __launch_bounds__(256) gemm_tf32(const float* __restrict__ A,
                                                 const float* __restrict__ Bw,
                                                 const float* __restrict__ bias,
                                                 float* __restrict__ out) {
    const int K = CC;
    const float* Ap = SCATTER ? A : (const float*)g_o;
    int m0 = blockIdx.y * 128, n0 = blockIdx.x * 128;
    float* Asm = sm_dyn;
    float* Bsm = sm_dyn + 2 * GA_FL;
    unsigned sbase = (unsigned)__cvta_generic_to_shared(sm_dyn);
    int tid = threadIdx.x;
    int wid = tid >> 5, lane = tid & 31;
    int lr = lane >> 2, lc = lane & 3;
    int warp_m = wid & 3, warp_n = wid >> 2;

    float c[2][8][4] = {};

    auto stage = [&](int buf, int k0) {
        unsigned a_s = sbase + (unsigned)(buf * GA_FL) * 4u;
        unsigned b_s = sbase + (unsigned)(2 * GA_FL + buf * GB_FL) * 4u;
        #pragma unroll
        for (int i = 0; i < 4; i++) {
            int f4 = tid + i * 256;              // 1024 f4 of A (128x32)
            int r = f4 >> 3, cg = f4 & 7;
            cp16(a_s + (unsigned)(r * GA_ST + cg * 4) * 4u,
                 &Ap[(size_t)(m0 + r) * K + k0 + cg * 4]);
        }
        #pragma unroll
        for (int i = 0; i < 4; i++) {
            int f4 = tid + i * 256;              // 1024 f4 of B (32x128)
            int r = f4 >> 5, cg = f4 & 31;
            cp16(b_s + (unsigned)(r * GB_ST + cg * 4) * 4u,
                 &Bw[(size_t)(k0 + r) * N + n0 + cg * 4]);
        }
        asm volatile("cp.async.commit_group;");
    };

    stage(0, 0);
    const int NCHUNK = K / 32;
    for (int ch = 0; ch < NCHUNK; ch++) {
        int buf = ch & 1;
        if (ch < NCHUNK - 1) {
            stage(buf ^ 1, (ch + 1) * 32);
            asm volatile("cp.async.wait_group 1;");
        } else {
            asm volatile("cp.async.wait_group 0;");
        }
        __syncthreads();

        const float* Aw = Asm + buf * GA_FL + (warp_m * 32) * GA_ST;
        const float* Bb = Bsm + buf * GB_FL;
        #pragma unroll
        for (int kk = 0; kk < 4; kk++) {
            int kf = kk * 8;
            unsigned a[2][4];
            #pragma unroll
            for (int mt = 0; mt < 2; mt++) {
                a[mt][0] = f2tf32(Aw[(mt * 16 + lr    ) * GA_ST + kf + lc    ]);
                a[mt][1] = f2tf32(Aw[(mt * 16 + lr + 8) * GA_ST + kf + lc    ]);
                a[mt][2] = f2tf32(Aw[(mt * 16 + lr    ) * GA_ST + kf + lc + 4]);
                a[mt][3] = f2tf32(Aw[(mt * 16 + lr + 8) * GA_ST + kf + lc + 4]);
            }
            unsigned bf[8][2];
            #pragma unroll
            for (int nt = 0; nt < 8; nt++) {
                int nn = warp_n * 64 + nt * 8 + lr;
                bf[nt][0] = f2tf32(Bb[(kf + lc    ) * GB_ST + nn]);
                bf[nt][1] = f2tf32(Bb[(kf + lc + 4) * GB_ST + nn]);
            }
            #pragma unroll
            for (int mt = 0; mt < 2; mt++)
                #pragma unroll
                for (int nt = 0; nt < 8; nt++)
                    mma_tf32(c[mt][nt], a[mt][0], a[mt][1], a[mt][2], a[mt][3],
                             bf[nt][0], bf[nt][1]);
        }
        __syncthreads();
    }

    // Epilogue
    int t = n0 >> 9;   // uniform per CTA when SCATTER
    #pragma unroll
    for (int mt = 0; mt < 2; mt++) {
        #pragma unroll
        for (int half = 0; half < 2; half++) {
            int row = m0 + warp_m * 32 + mt * 16 + lr + half * 8;
            #pragma unroll
            for (int nt = 0; nt < 8; nt++) {
                int col = n0 + warp_n * 64 + nt * 8 + 2 * lc;
                float v0 = c[mt][nt][half * 2 + 0] + bias[col];
                float v1 = c[mt][nt][half * 2 + 1] + bias[col + 1];
                if (SCATTER) {
                    int b = row >> 11, l = row & 2047;
                    int h = (col & 511) >> 6;
                    int d = col & 63, d1 = d + 1;
                    int bh = b * HH + h;
                    if (t == 0) {
                        *(float2*)&g_q[((size_t)bh * LL + l) * DD + d] =
                            make_float2(v0, v1);
                        int qt = l >> 7, r = l & 127;
                        int w = r >> 4, lr2 = r & 7, hf = (r >> 3) & 1;
                        float* qp = g_qp + ((size_t)(bh * NQ + qt)) * 8192 + w * 1024;
                        qp[(d  >> 3) * 128 + (lr2 * 4 + (d  & 3)) * 4 + hf + 2 * ((d  >> 2) & 1)]
                            = tf32f(v0 * SCALE);
                        qp[(d1 >> 3) * 128 + (lr2 * 4 + (d1 & 3)) * 4 + hf + 2 * ((d1 >> 2) & 1)]
                            = tf32f(v1 * SCALE);
                    } else if (t == 1) {
                        *(float2*)&g_k[((size_t)bh * LL + l) * DD + d] =
                            make_float2(v0, v1);
                        // paired-fragment layout [kk][ntp][lane][4]
                        int kb = l >> 6, n = l & 63;
                        int kk = d >> 3, lcc = d & 3, hi = (d >> 2) & 1;
                        int nt2 = n >> 3, lrr = n & 7;
                        float* kp = g_kp + ((size_t)(bh * NK + kb)) * 4096
                                  + kk * 512 + (nt2 >> 1) * 128
                                  + (lrr * 4 + lcc) * 4 + (nt2 & 1) * 2 + hi;
                        kp[0] = tf32f(v0);
                        kp[4] = tf32f(v1);      // d+1 -> lane+1 -> +4 floats
                    } else {
                        int kb = l >> 6, k64 = l & 63;
                        int kk = k64 >> 3, lcv = k64 & 3, hi = (k64 >> 2) & 1;
                        int ntv = d >> 3, lrv = d & 7;
                        float* vp = g_vp + ((size_t)(bh * NK + kb)) * 4096
                                  + kk * 512 + (ntv >> 1) * 128
                                  + (lrv * 4 + lcv) * 4 + (ntv & 1) * 2 + hi;
                        vp[0]  = tf32f(v0);
                        vp[16] = tf32f(v1);     // d+1 -> lrv+1 -> lane+4 -> +16
                    }
                } else {
                    *(float2*)&out[(size_t)row * N + col] = make_float2(v0, v1);
                }
            }
        }
    }
}

// ---------------------------------------------------------------------------
// Kernel 2a: per-block mean + min-cosine.
// ---------------------------------------------------------------------------
__global__ void __launch_bounds__(256) meansim_kernel() {
    int bh = blockIdx.y;
    int j  = blockIdx.x;
    bool isQ = j < NQ;
    int blk  = isQ ? j : j - NQ;
    int rows = isQ ? 128 : 64;
    const float* base = (isQ ? g_q : g_k) + (size_t)bh * LL * DD + (size_t)blk * rows * DD;
    __shared__ float psum[256];
    __shared__ float mean[64];
    __shared__ float nrm;
    __shared__ float simv;
    int tid = threadIdx.x;
    if (tid == 0) simv = 1e30f;

    {
        int d = tid & 63, rg = tid >> 6;
        float acc = 0.f;
        for (int r = rg; r < rows; r += 4) acc += base[r * DD + d];
        psum[tid] = acc;
    }
    __syncthreads();
    if (tid < 64) {
        float m = (psum[tid] + psum[tid + 64] + psum[tid + 128] + psum[tid + 192])
                  * (1.f / rows);
        mean[tid] = m;
        float* gm = isQ ? &g_qm[bh][blk][0] : &g_km[bh][blk][0];
        gm[tid] = m;
    }
    __syncthreads();
    if (tid < 32) {
        float s = mean[tid] * mean[tid] + mean[tid + 32] * mean[tid + 32];
        #pragma unroll
        for (int o = 16; o >= 1; o >>= 1) s += __shfl_xor_sync(0xffffffffu, s, o);
        if (tid == 0) nrm = sqrtf(s);
    }
    __syncthreads();
    float mnorm = nrm;

    float cosv;
    if (isQ) {
        int row = tid >> 1, half = tid & 1;
        const float* p  = base + row * DD + half * 32;
        const float* mp = mean + half * 32;
        float dot = 0.f, nn = 0.f;
        #pragma unroll
        for (int d = 0; d < 32; d++) { float v = p[d]; dot += v * mp[d]; nn += v * v; }
        dot += __shfl_xor_sync(0xffffffffu, dot, 1);
        nn  += __shfl_xor_sync(0xffffffffu, nn,  1);
        cosv = dot / ((sqrtf(nn) + 1e-6f) * (mnorm + 1e-6f));
    } else {
        int row = tid >> 2, qd = tid & 3;
        const float* p  = base + row * DD + qd * 16;
        const float* mp = mean + qd * 16;
        float dot = 0.f, nn = 0.f;
        #pragma unroll
        for (int d = 0; d < 16; d++) { float v = p[d]; dot += v * mp[d]; nn += v * v; }
        dot += __shfl_xor_sync(0xffffffffu, dot, 1);
        dot += __shfl_xor_sync(0xffffffffu, dot, 2);
        nn  += __shfl_xor_sync(0xffffffffu, nn,  1);
        nn  += __shfl_xor_sync(0xffffffffu, nn,  2);
        cosv = dot / ((sqrtf(nn) + 1e-6f) * (mnorm + 1e-6f));
    }
    #pragma unroll
    for (int o = 16; o >= 1; o >>= 1)
        cosv = fminf(cosv, __shfl_xor_sync(0xffffffffu, cosv, o));
    if ((tid & 31) == 0) atomicMinFloat(&simv, cosv);
    __syncthreads();
    if (tid == 0) {
        if (isQ) g_qsim[bh][blk] = simv; else g_ksim[bh][blk] = simv;
    }
}

// ---------------------------------------------------------------------------
// Kernel 2b: pooled softmax + CDF keep -> block mask.
// ---------------------------------------------------------------------------
__global__ void __launch_bounds__(256) mask_kernel() {
    int bh = blockIdx.x;
    __shared__ float pooled[NQ][NK];
    __shared__ float qs[NQ], kss[NK];
    int tid = threadIdx.x;
    if (tid < NQ) qs[tid]  = g_qsim[bh][tid];
    if (tid < NK) kss[tid] = g_ksim[bh][tid];
    for (int e = tid; e < NQ * NK; e += 256) {
        int qi = e >> 5, ki = e & 31;
        const float* a = g_qm[bh][qi];
        const float* b = g_km[bh][ki];
        float dot = 0.f;
        #pragma unroll
        for (int d = 0; d < DD; d++) dot += a[d] * b[d];
        pooled[qi][ki] = dot * SCALE;
    }
    __syncthreads();
    if (tid < NQ) {
        float vals[NK]; int idx[NK];
        float mx = -CUDART_INF_F;
        for (int i = 0; i < NK; i++) mx = fmaxf(mx, pooled[tid][i]);
        float sum = 0.f;
        for (int i = 0; i < NK; i++) { vals[i] = expf(pooled[tid][i] - mx); sum += vals[i]; }
        float inv = 1.f / sum;
        for (int i = 0; i < NK; i++) { vals[i] *= inv; idx[i] = i; }
        for (int i = 1; i < NK; i++) {
            float kv = vals[i]; int ki = idx[i];
            int j = i - 1;
            while (j >= 0 && vals[j] < kv) { vals[j+1] = vals[j]; idx[j+1] = idx[j]; j--; }
            vals[j+1] = kv; idx[j+1] = ki;
        }
        unsigned keep = 0u;
        float csum = 0.f;
        for (int i = 0; i < NK; i++) {
            if (csum < CDFTH) keep |= (1u << idx[i]);
            csum += vals[i];
        }
        bool qself = qs[tid] > SIMTH;
        int* mrow = g_mask + (bh * NQ + tid) * NK;
        for (int ki = 0; ki < NK; ki++) {
            bool kself = kss[ki] > SIMTH;
            mrow[ki] = (((keep >> ki) & 1u) || !qself || !kself) ? 1 : 0;
        }
    }
}

// ---------------------------------------------------------------------------
// Kernel 3: block-sparse flash attention, tf32 mma.
// R14 structure (Q in regs, K/V cp.async double-buffered smem staging) +
// R15 paired-fragment K/V layout: every K/V smem read is an LDS.128
// feeding 4 mma.
// grid = (16 q-tiles of 128 rows, 16 bh), 128 threads = 4 warps.
// smem: K0/K1[4096 ea] | V0/V1[4096 ea] | Pp[4 w][1024] = 20480 fl = 80 KB
//   -> 2 CTAs/SM.
// ---------------------------------------------------------------------------
#define ATT_KV_FL 4096
#define ATT_SMEM_FLOATS (4*ATT_KV_FL + 4*1024)   // 20480
#define ATT_SMEM_BYTES  (ATT_SMEM_FLOATS * 4)    // 81920

__global__ void __launch_bounds__(128, 2) attn_tf32() {
    const int qb = blockIdx.x;
    const int bh = blockIdx.y;
    const int b = bh >> 3, h = bh & 7;
    const int tid  = threadIdx.x;
    const int wid  = tid >> 5;          // 0..3, warp owns rows wid*32..wid*32+31
    const int lane = tid & 31;
    const int lr = lane >> 2;
    const int lc = lane & 3;

    float* Kbuf = sm_dyn;                                   // [2][4096]
    float* Vbuf = sm_dyn + 2 * ATT_KV_FL;                   // [2][4096]
    float* PpW  = Vbuf + 2 * ATT_KV_FL + wid * 1024;        // [4 slice][2 g][2 c2][32 L][2]
    unsigned sbase  = (unsigned)__cvta_generic_to_shared(sm_dyn);
    unsigned kbuf_u = sbase;
    unsigned vbuf_u = sbase + 2u * ATT_KV_FL * 4u;

    __shared__ int s_list[NK];
    __shared__ int s_nk;

    // Q A-fragments -> registers (loop-invariant; coalesced LDG.128)
    unsigned qreg[2][8][4];
    {
        const float* qg = g_qp + ((size_t)(bh * NQ + qb)) * 8192 + (2 * wid) * 1024;
        #pragma unroll
        for (int g = 0; g < 2; g++)
            #pragma unroll
            for (int kk = 0; kk < 8; kk++) {
                float4 v = *(const float4*)(qg + g * 1024 + kk * 128 + lane * 4);
                qreg[g][kk][0] = __float_as_uint(v.x);
                qreg[g][kk][1] = __float_as_uint(v.y);
                qreg[g][kk][2] = __float_as_uint(v.z);
                qreg[g][kk][3] = __float_as_uint(v.w);
            }
    }

    // Kept-block list
    const int* mrow = g_mask + (bh * NQ + qb) * NK;
    if (tid == 0) {
        int c = 0;
        for (int i = 0; i < NK; i++) if (mrow[i]) s_list[c++] = i;
        s_nk = c;
    }
    __syncthreads();
    const int nkeep = s_nk;

    const float* kgp = g_kp + (size_t)bh * NK * 4096;
    const float* vgp = g_vp + (size_t)bh * NK * 4096;

    auto stage_kv = [&](int buf, int kb) {
        const float* ks = kgp + (size_t)kb * 4096;
        const float* vs = vgp + (size_t)kb * 4096;
        unsigned ko = kbuf_u + (unsigned)(buf * ATT_KV_FL) * 4u;
        unsigned vo = vbuf_u + (unsigned)(buf * ATT_KV_FL) * 4u;
        #pragma unroll
        for (int i = 0; i < 8; i++) {
            unsigned off = (unsigned)(tid + i * 128) * 16u;
            cp16(ko + off, ks + (tid + i * 128) * 4);
            cp16(vo + off, vs + (tid + i * 128) * 4);
        }
        asm volatile("cp.async.commit_group;");
    };

    stage_kv(0, s_list[0]);

    float o[2][8][4];
    #pragma unroll
    for (int g = 0; g < 2; g++)
        #pragma unroll
        for (int nt = 0; nt < 8; nt++)
            #pragma unroll
            for (int j = 0; j < 4; j++) o[g][nt][j] = 0.f;
    float m[4] = {-CUDART_INF_F, -CUDART_INF_F, -CUDART_INF_F, -CUDART_INF_F};
    float l[4] = {0.f, 0.f, 0.f, 0.f};

    for (int i = 0; i < nkeep; i++) {
        int buf = i & 1;
        asm volatile("cp.async.wait_group 0;");
        __syncthreads();               // staged data visible; prev iter reads done
        if (i + 1 < nkeep) stage_kv(buf ^ 1, s_list[i + 1]);

        const float4* Kp4 = (const float4*)(Kbuf + buf * ATT_KV_FL);
        const float4* Vp4 = (const float4*)(Vbuf + buf * ATT_KV_FL);

        // ---- S = Q K^T : 32 rows x 64 kpos per warp (LDS.128 -> 4 mma) ----
        float sc[2][8][4];
        #pragma unroll
        for (int g = 0; g < 2; g++)
            #pragma unroll
            for (int nt = 0; nt < 8; nt++)
                #pragma unroll
                for (int j = 0; j < 4; j++) sc[g][nt][j] = 0.f;

        #pragma unroll
        for (int kk = 0; kk < 8; kk++) {
            #pragma unroll
            for (int ntp = 0; ntp < 4; ntp++) {
                float4 kv = Kp4[kk * 128 + ntp * 32 + lane];
                unsigned b0 = __float_as_uint(kv.x), b1 = __float_as_uint(kv.y);
                unsigned b2 = __float_as_uint(kv.z), b3 = __float_as_uint(kv.w);
                int nte = 2 * ntp, nto = nte + 1;
                mma_tf32(sc[0][nte], qreg[0][kk][0], qreg[0][kk][1],
                         qreg[0][kk][2], qreg[0][kk][3], b0, b1);
                mma_tf32(sc[1][nte], qreg[1][kk][0], qreg[1][kk][1],
                         qreg[1][kk][2], qreg[1][kk][3], b0, b1);
                mma_tf32(sc[0][nto], qreg[0][kk][0], qreg[0][kk][1],
                         qreg[0][kk][2], qreg[0][kk][3], b2, b3);
                mma_tf32(sc[1][nto], qreg[1][kk][0], qreg[1][kk][1],
                         qreg[1][kk][2], qreg[1][kk][3], b2, b3);
            }
        }

        // ---- Online softmax maxes (4 row-groups: lr, lr+8, 16+lr, 24+lr) ----
        float r0 = -CUDART_INF_F, r1 = -CUDART_INF_F;
        float r2 = -CUDART_INF_F, r3 = -CUDART_INF_F;
        #pragma unroll
        for (int nt = 0; nt < 8; nt++) {
            r0 = fmaxf(r0, fmaxf(sc[0][nt][0], sc[0][nt][1]));
            r1 = fmaxf(r1, fmaxf(sc[0][nt][2], sc[0][nt][3]));
            r2 = fmaxf(r2, fmaxf(sc[1][nt][0], sc[1][nt][1]));
            r3 = fmaxf(r3, fmaxf(sc[1][nt][2], sc[1][nt][3]));
        }
        r0 = fmaxf(r0, __shfl_xor_sync(0xffffffffu, r0, 1));
        r0 = fmaxf(r0, __shfl_xor_sync(0xffffffffu, r0, 2));
        r1 = fmaxf(r1, __shfl_xor_sync(0xffffffffu, r1, 1));
        r1 = fmaxf(r1, __shfl_xor_sync(0xffffffffu, r1, 2));
        r2 = fmaxf(r2, __shfl_xor_sync(0xffffffffu, r2, 1));
        r2 = fmaxf(r2, __shfl_xor_sync(0xffffffffu, r2, 2));
        r3 = fmaxf(r3, __shfl_xor_sync(0xffffffffu, r3, 1));
        r3 = fmaxf(r3, __shfl_xor_sync(0xffffffffu, r3, 2));
        float mn0 = fmaxf(m[0], r0), mn1 = fmaxf(m[1], r1);
        float mn2 = fmaxf(m[2], r2), mn3 = fmaxf(m[3], r3);
        float c0 = __expf(m[0] - mn0), c1 = __expf(m[1] - mn1);
        float c2 = __expf(m[2] - mn2), c3 = __expf(m[3] - mn3);
        #pragma unroll
        for (int nt = 0; nt < 8; nt++) {
            o[0][nt][0] *= c0; o[0][nt][1] *= c0;
            o[0][nt][2] *= c1; o[0][nt][3] *= c1;
            o[1][nt][0] *= c2; o[1][nt][1] *= c2;
            o[1][nt][2] *= c3; o[1][nt][3] *= c3;
        }

        // ---- PV in two 4-slice batches ----
        float s0 = 0.f, s1 = 0.f, s2 = 0.f, s3 = 0.f;
        #pragma unroll
        for (int ph = 0; ph < 2; ph++) {
            int base_nt = ph * 4;
            if (ph) __syncwarp();     // phase-A reads done before overwrite
            #pragma unroll
            for (int j = 0; j < 4; j++) {
                int nt = base_nt + j;
                float p00 = __expf(sc[0][nt][0] - mn0);
                float p01 = __expf(sc[0][nt][1] - mn0);
                float p02 = __expf(sc[0][nt][2] - mn1);
                float p03 = __expf(sc[0][nt][3] - mn1);
                float p10 = __expf(sc[1][nt][0] - mn2);
                float p11 = __expf(sc[1][nt][1] - mn2);
                float p12 = __expf(sc[1][nt][2] - mn3);
                float p13 = __expf(sc[1][nt][3] - mn3);
                s0 += p00 + p01; s1 += p02 + p03;
                s2 += p10 + p11; s3 += p12 + p13;
                float* Pb0 = PpW + j * 256;          // g=0
                float* Pb1 = PpW + j * 256 + 128;    // g=1
                *(float2*)(Pb0 +      lane * 2) = make_float2(tf32f(p00), tf32f(p02));
                *(float2*)(Pb0 + 64 + lane * 2) = make_float2(tf32f(p01), tf32f(p03));
                *(float2*)(Pb1 +      lane * 2) = make_float2(tf32f(p10), tf32f(p12));
                *(float2*)(Pb1 + 64 + lane * 2) = make_float2(tf32f(p11), tf32f(p13));
            }
            __syncwarp();
            #pragma unroll
            for (int j = 0; j < 4; j++) {
                int kk = base_nt + j;
                int poff = (lc & 1) * 64 + (lr * 4 + (lc >> 1)) * 2;
                const float* pb0 = PpW + j * 256 + poff;
                const float* pb1 = pb0 + 128;
                float2 A01 = *(const float2*)pb0;
                float2 A23 = *(const float2*)(pb0 + 4);
                float2 B01 = *(const float2*)pb1;
                float2 B23 = *(const float2*)(pb1 + 4);
                unsigned aA0 = __float_as_uint(A01.x), aA1 = __float_as_uint(A01.y);
                unsigned aA2 = __float_as_uint(A23.x), aA3 = __float_as_uint(A23.y);
                unsigned aB0 = __float_as_uint(B01.x), aB1 = __float_as_uint(B01.y);
                unsigned aB2 = __float_as_uint(B23.x), aB3 = __float_as_uint(B23.y);
                #pragma unroll
                for (int ntp2 = 0; ntp2 < 4; ntp2++) {
                    float4 vv = Vp4[kk * 128 + ntp2 * 32 + lane];
                    unsigned b0 = __float_as_uint(vv.x), b1 = __float_as_uint(vv.y);
                    unsigned b2 = __float_as_uint(vv.z), b3 = __float_as_uint(vv.w);
                    int nte = 2 * ntp2, nto = nte + 1;
                    mma_tf32(o[0][nte], aA0, aA1, aA2, aA3, b0, b1);
                    mma_tf32(o[1][nte], aB0, aB1, aB2, aB3, b0, b1);
                    mma_tf32(o[0][nto], aA0, aA1, aA2, aA3, b2, b3);
                    mma_tf32(o[1][nto], aB0, aB1, aB2, aB3, b2, b3);
                }
            }
        }
        s0 += __shfl_xor_sync(0xffffffffu, s0, 1);
        s0 += __shfl_xor_sync(0xffffffffu, s0, 2);
        s1 += __shfl_xor_sync(0xffffffffu, s1, 1);
        s1 += __shfl_xor_sync(0xffffffffu, s1, 2);
        s2 += __shfl_xor_sync(0xffffffffu, s2, 1);
        s2 += __shfl_xor_sync(0xffffffffu, s2, 2);
        s3 += __shfl_xor_sync(0xffffffffu, s3, 1);
        s3 += __shfl_xor_sync(0xffffffffu, s3, 2);
        l[0] = l[0] * c0 + s0;
        l[1] = l[1] * c1 + s1;
        l[2] = l[2] * c2 + s2;
        l[3] = l[3] * c3 + s3;
        m[0] = mn0; m[1] = mn1; m[2] = mn2; m[3] = mn3;
    }

    // Epilogue: normalize and scatter to g_o
    float inv0 = 1.f / l[0], inv1 = 1.f / l[1];
    float inv2 = 1.f / l[2], inv3 = 1.f / l[3];
    int r0r = qb * 128 + wid * 32 + lr;
    float* og = g_o + (size_t)b * LL * CC + h * DD;
    #pragma unroll
    for (int nt = 0; nt < 8; nt++) {
        float2 w0 = make_float2(o[0][nt][0] * inv0, o[0][nt][1] * inv0);
        float2 w1 = make_float2(o[0][nt][2] * inv1, o[0][nt][3] * inv1);
        float2 w2 = make_float2(o[1][nt][0] * inv2, o[1][nt][1] * inv2);
        float2 w3 = make_float2(o[1][nt][2] * inv3, o[1][nt][3] * inv3);
        *(float2*)&og[(size_t)(r0r     ) * CC + nt * 8 + 2 * lc] = w0;
        *(float2*)&og[(size_t)(r0r +  8) * CC + nt * 8 + 2 * lc] = w1;
        *(float2*)&og[(size_t)(r0r + 16) * CC + nt * 8 + 2 * lc] = w2;
        *(float2*)&og[(size_t)(r0r + 24) * CC + nt * 8 + 2 * lc] = w3;
    }
}

// ---------------------------------------------------------------------------
extern "C" void kernel_launch(void* const* d_in, const int* in_sizes, int n_in,
                              void* d_out, int out_size) {
    const float* x     = (const float*)d_in[0];
    const float* Wqkv  = (const float*)d_in[1];
    const float* bqkv  = (const float*)d_in[2];
    const float* Wproj = (const float*)d_in[3];
    const float* bproj = (const float*)d_in[4];
    float* out = (float*)d_out;

    cudaFuncSetAttribute(attn_tf32, cudaFuncAttributeMaxDynamicSharedMemorySize,
                         ATT_SMEM_BYTES);
    cudaFuncSetAttribute(gemm_tf32<NQKV, true>,
                         cudaFuncAttributeMaxDynamicSharedMemorySize, GEMM_SMEM_BYTES);
    cudaFuncSetAttribute(gemm_tf32<CC, false>,
                         cudaFuncAttributeMaxDynamicSharedMemorySize, GEMM_SMEM_BYTES);

    gemm_tf32<NQKV, true><<<dim3(NQKV / 128, MM / 128), 256, GEMM_SMEM_BYTES>>>(
        x, Wqkv, bqkv, nullptr);
    meansim_kernel<<<dim3(NQ + NK, BB * HH), 256>>>();
    mask_kernel<<<BB * HH, 256>>>();
    attn_tf32<<<dim3(NQ, BB * HH), 128, ATT_SMEM_BYTES>>>();
    gemm_tf32<CC, false><<<dim3(CC / 128, MM / 128), 256, GEMM_SMEM_BYTES>>>(
        nullptr, Wproj, bproj, out);
}

// round 17
// speedup vs baseline: 1.3768x; 1.2458x over previous
#include <cuda_runtime.h>
#include <cuda_bf16.h>
#include <cuda_fp16.h>
#include <math_constants.h>

// Problem constants
#define BB   2
#define LL   2048
#define CC   512
#define HH   8
#define DD   64
#define MM   (BB*LL)          // 4096 rows
#define NQKV (3*CC)           // 1536
#define NQ   16               // L/128 (mask Q-block granularity)
#define NK   32               // L/64
#define SCALE 0.125f          // D^-0.5
#define SIMTH 0.6f
#define CDFTH 0.98f

// Scratch (allocation-free rule -> device globals)
__device__ float    g_q[BB*HH*LL*DD];       // raw [B,H,L,D] (meansim)
__device__ float    g_k[BB*HH*LL*DD];       // raw [B,H,L,D] (meansim)
__device__ unsigned g_qph[BB*HH*NQ*4096];   // Q fp16 A-frags (m16n8k16)
__device__ unsigned g_kph[BB*HH*NK*2048];   // K fp16 paired B-frags
__device__ unsigned g_vph[BB*HH*NK*2048];   // V fp16 paired B-frags
__device__ float    g_o[BB*LL*CC];          // [B,L,C]
__device__ int      g_mask[BB*HH*NQ*NK];    // 1 = keep block
__device__ float    g_qm[BB*HH][NQ][DD];
__device__ float    g_km[BB*HH][NK][DD];
__device__ float    g_qsim[BB*HH][NQ];
__device__ float    g_ksim[BB*HH][NK];

__device__ __forceinline__ unsigned f2tf32(float x) {
    unsigned r;
    asm("cvt.rna.tf32.f32 %0, %1;" : "=r"(r) : "f"(x));
    return r;
}
// pack two f32 -> f16x2 (lo = first arg)
__device__ __forceinline__ unsigned f2h2(float lo, float hi) {
    unsigned r;
    asm("cvt.rn.f16x2.f32 %0, %1, %2;" : "=r"(r) : "f"(hi), "f"(lo));
    return r;
}

__device__ __forceinline__ void mma_tf32(float c[4],
                                         unsigned a0, unsigned a1, unsigned a2, unsigned a3,
                                         unsigned b0, unsigned b1) {
    asm volatile(
        "mma.sync.aligned.m16n8k8.row.col.f32.tf32.tf32.f32 "
        "{%0,%1,%2,%3}, {%4,%5,%6,%7}, {%8,%9}, {%0,%1,%2,%3};"
        : "+f"(c[0]), "+f"(c[1]), "+f"(c[2]), "+f"(c[3])
        : "r"(a0), "r"(a1), "r"(a2), "r"(a3), "r"(b0), "r"(b1));
}

__device__ __forceinline__ void mma_f16(float c[4],
                                        unsigned a0, unsigned a1, unsigned a2, unsigned a3,
                                        unsigned b0, unsigned b1) {
    asm volatile(
        "mma.sync.aligned.m16n8k16.row.col.f32.f16.f16.f32 "
        "{%0,%1,%2,%3}, {%4,%5,%6,%7}, {%8,%9}, {%0,%1,%2,%3};"
        : "+f"(c[0]), "+f"(c[1]), "+f"(c[2]), "+f"(c[3])
        : "r"(a0), "r"(a1), "r"(a2), "r"(a3), "r"(b0), "r"(b1));
}

__device__ __forceinline__ void cp16(unsigned smem_dst, const void* gsrc) {
    asm volatile("cp.async.ca.shared.global [%0], [%1], 16;"
                 :: "r"(smem_dst), "l"(gsrc));
}

__device__ __forceinline__ void atomicMinFloat(float* addr, float val) {
    int* ia = (int*)addr;
    int old = *ia;
    while (__int_as_float(old) > val) {
        int assumed = old;
        old = atomicCAS(ia, assumed, __float_as_int(val));
        if (old == assumed) break;
    }
}

// ---------------------------------------------------------------------------
// tf32 tensor-core GEMM: C[M,N] = A[M,K=512] @ B[K,N] + bias
// 128x128 tile, 256 threads = 8 warps (4M x 2N), warp tile 32x64,
// cp.async double-buffered.  SCATTER=true: writes raw q/k + fp16 frag packs.
// ---------------------------------------------------------------------------
#define GA_ST 36
#define GB_ST 136
#define GA_FL (128*GA_ST)          // 4608
#define GB_FL (32*GB_ST)           // 4352
#define GEMM_SMEM_FLOATS (2*GA_FL + 2*GB_FL)
#define GEMM_SMEM_BYTES  (GEMM_SMEM_FLOATS*4)   // 71680

extern __shared__ float sm_dyn[];

template<int N, bool SCATTER>
__global__ void __launch_bounds__(256) gemm_tf32(const float* __restrict__ A,
                                                 const float* __restrict__ Bw,
                                                 const float* __restrict__ bias,
                                                 float* __restrict__ out) {
    const int K = CC;
    const float* Ap = SCATTER ? A : (const float*)g_o;
    int m0 = blockIdx.y * 128, n0 = blockIdx.x * 128;
    float* Asm = sm_dyn;
    float* Bsm = sm_dyn + 2 * GA_FL;
    unsigned sbase = (unsigned)__cvta_generic_to_shared(sm_dyn);
    int tid = threadIdx.x;
    int wid = tid >> 5, lane = tid & 31;
    int lr = lane >> 2, lc = lane & 3;
    int warp_m = wid & 3, warp_n = wid >> 2;

    float c[2][8][4] = {};

    auto stage = [&](int buf, int k0) {
        unsigned a_s = sbase + (unsigned)(buf * GA_FL) * 4u;
        unsigned b_s = sbase + (unsigned)(2 * GA_FL + buf * GB_FL) * 4u;
        #pragma unroll
        for (int i = 0; i < 4; i++) {
            int f4 = tid + i * 256;
            int r = f4 >> 3, cg = f4 & 7;
            cp16(a_s + (unsigned)(r * GA_ST + cg * 4) * 4u,
                 &Ap[(size_t)(m0 + r) * K + k0 + cg * 4]);
        }
        #pragma unroll
        for (int i = 0; i < 4; i++) {
            int f4 = tid + i * 256;
            int r = f4 >> 5, cg = f4 & 31;
            cp16(b_s + (unsigned)(r * GB_ST + cg * 4) * 4u,
                 &Bw[(size_t)(k0 + r) * N + n0 + cg * 4]);
        }
        asm volatile("cp.async.commit_group;");
    };

    stage(0, 0);
    const int NCHUNK = K / 32;
    for (int ch = 0; ch < NCHUNK; ch++) {
        int buf = ch & 1;
        if (ch < NCHUNK - 1) {
            stage(buf ^ 1, (ch + 1) * 32);
            asm volatile("cp.async.wait_group 1;");
        } else {
            asm volatile("cp.async.wait_group 0;");
        }
        __syncthreads();

        const float* Aw = Asm + buf * GA_FL + (warp_m * 32) * GA_ST;
        const float* Bb = Bsm + buf * GB_FL;
        #pragma unroll
        for (int kk = 0; kk < 4; kk++) {
            int kf = kk * 8;
            unsigned a[2][4];
            #pragma unroll
            for (int mt = 0; mt < 2; mt++) {
                a[mt][0] = f2tf32(Aw[(mt * 16 + lr    ) * GA_ST + kf + lc    ]);
                a[mt][1] = f2tf32(Aw[(mt * 16 + lr + 8) * GA_ST + kf + lc    ]);
                a[mt][2] = f2tf32(Aw[(mt * 16 + lr    ) * GA_ST + kf + lc + 4]);
                a[mt][3] = f2tf32(Aw[(mt * 16 + lr + 8) * GA_ST + kf + lc + 4]);
            }
            unsigned bf[8][2];
            #pragma unroll
            for (int nt = 0; nt < 8; nt++) {
                int nn = warp_n * 64 + nt * 8 + lr;
                bf[nt][0] = f2tf32(Bb[(kf + lc    ) * GB_ST + nn]);
                bf[nt][1] = f2tf32(Bb[(kf + lc + 4) * GB_ST + nn]);
            }
            #pragma unroll
            for (int mt = 0; mt < 2; mt++)
                #pragma unroll
                for (int nt = 0; nt < 8; nt++)
                    mma_tf32(c[mt][nt], a[mt][0], a[mt][1], a[mt][2], a[mt][3],
                             bf[nt][0], bf[nt][1]);
        }
        __syncthreads();
    }

    // Epilogue
    int t = n0 >> 9;   // uniform per CTA when SCATTER
    #pragma unroll
    for (int mt = 0; mt < 2; mt++) {
        #pragma unroll
        for (int half = 0; half < 2; half++) {
            int row = m0 + warp_m * 32 + mt * 16 + lr + half * 8;
            #pragma unroll
            for (int nt = 0; nt < 8; nt++) {
                int col = n0 + warp_n * 64 + nt * 8 + 2 * lc;
                float v0 = c[mt][nt][half * 2 + 0] + bias[col];
                float v1 = c[mt][nt][half * 2 + 1] + bias[col + 1];
                if (SCATTER) {
                    int b = row >> 11, l = row & 2047;
                    int h = (col & 511) >> 6;
                    int d = col & 63;
                    int bh = b * HH + h;
                    if (t == 0) {
                        *(float2*)&g_q[((size_t)bh * LL + l) * DD + d] =
                            make_float2(v0, v1);
                        // fp16 A-frag pack (m16n8k16)
                        int qt = l >> 7, r = l & 127;
                        int chunk = r >> 4, row16 = r & 15;
                        int kk = d >> 4, d16 = d & 15;
                        int reg = (row16 >= 8 ? 1 : 0) + (d16 >= 8 ? 2 : 0);
                        int lanei = (row16 & 7) * 4 + ((d16 & 7) >> 1);
                        g_qph[((size_t)(bh * NQ + qt)) * 4096
                              + ((chunk * 4 + kk) * 32 + lanei) * 4 + reg]
                            = f2h2(v0 * SCALE, v1 * SCALE);
                    } else if (t == 1) {
                        *(float2*)&g_k[((size_t)bh * LL + l) * DD + d] =
                            make_float2(v0, v1);
                        // fp16 paired B-frag pack: [kk][ntp][lane][4slot]
                        int kb = l >> 6, n = l & 63;
                        int kk = d >> 4, d16 = d & 15;
                        int b1f = (d16 >= 8) ? 1 : 0;
                        int lcp = (d16 & 7) >> 1;
                        int ntq = n >> 3, ntp = ntq >> 1, odd = ntq & 1;
                        int lanei = (n & 7) * 4 + lcp;
                        g_kph[((size_t)(bh * NK + kb)) * 2048
                              + kk * 512 + ntp * 128 + lanei * 4 + odd * 2 + b1f]
                            = f2h2(v0, v1);
                    } else {
                        // V: [kk(kpos)][ntp(dim)][lane][4slot], two u16 stores
                        int kb = l >> 6, n = l & 63;     // n = kpos
                        int kk = n >> 4, n16 = n & 15;
                        int b1f = (n16 >= 8) ? 1 : 0;
                        int lcp = (n16 & 7) >> 1, hh = n16 & 1;
                        int nt0 = d >> 3, ntp0 = nt0 >> 1, odd0 = nt0 & 1;
                        int lane0 = (d & 7) * 4 + lcp;
                        __half* vh = (__half*)(g_vph + ((size_t)(bh * NK + kb)) * 2048);
                        int hidx = (kk * 512 + ntp0 * 128 + lane0 * 4 + odd0 * 2 + b1f) * 2 + hh;
                        vh[hidx]      = __float2half_rn(v0);
                        vh[hidx + 32] = __float2half_rn(v1);  // lane0+4 -> +16 u32 -> +32 half
                    }
                } else {
                    *(float2*)&out[(size_t)row * N + col] = make_float2(v0, v1);
                }
            }
        }
    }
}

// ---------------------------------------------------------------------------
// Kernel 2a: per-block mean + min-cosine.
// ---------------------------------------------------------------------------
__global__ void __launch_bounds__(256) meansim_kernel() {
    int bh = blockIdx.y;
    int j  = blockIdx.x;
    bool isQ = j < NQ;
    int blk  = isQ ? j : j - NQ;
    int rows = isQ ? 128 : 64;
    const float* base = (isQ ? g_q : g_k) + (size_t)bh * LL * DD + (size_t)blk * rows * DD;
    __shared__ float psum[256];
    __shared__ float mean[64];
    __shared__ float nrm;
    __shared__ float simv;
    int tid = threadIdx.x;
    if (tid == 0) simv = 1e30f;

    {
        int d = tid & 63, rg = tid >> 6;
        float acc = 0.f;
        for (int r = rg; r < rows; r += 4) acc += base[r * DD + d];
        psum[tid] = acc;
    }
    __syncthreads();
    if (tid < 64) {
        float m = (psum[tid] + psum[tid + 64] + psum[tid + 128] + psum[tid + 192])
                  * (1.f / rows);
        mean[tid] = m;
        float* gm = isQ ? &g_qm[bh][blk][0] : &g_km[bh][blk][0];
        gm[tid] = m;
    }
    __syncthreads();
    if (tid < 32) {
        float s = mean[tid] * mean[tid] + mean[tid + 32] * mean[tid + 32];
        #pragma unroll
        for (int o = 16; o >= 1; o >>= 1) s += __shfl_xor_sync(0xffffffffu, s, o);
        if (tid == 0) nrm = sqrtf(s);
    }
    __syncthreads();
    float mnorm = nrm;

    float cosv;
    if (isQ) {
        int row = tid >> 1, half = tid & 1;
        const float* p  = base + row * DD + half * 32;
        const float* mp = mean + half * 32;
        float dot = 0.f, nn = 0.f;
        #pragma unroll
        for (int d = 0; d < 32; d++) { float v = p[d]; dot += v * mp[d]; nn += v * v; }
        dot += __shfl_xor_sync(0xffffffffu, dot, 1);
        nn  += __shfl_xor_sync(0xffffffffu, nn,  1);
        cosv = dot / ((sqrtf(nn) + 1e-6f) * (mnorm + 1e-6f));
    } else {
        int row = tid >> 2, qd = tid & 3;
        const float* p  = base + row * DD + qd * 16;
        const float* mp = mean + qd * 16;
        float dot = 0.f, nn = 0.f;
        #pragma unroll
        for (int d = 0; d < 16; d++) { float v = p[d]; dot += v * mp[d]; nn += v * v; }
        dot += __shfl_xor_sync(0xffffffffu, dot, 1);
        dot += __shfl_xor_sync(0xffffffffu, dot, 2);
        nn  += __shfl_xor_sync(0xffffffffu, nn,  1);
        nn  += __shfl_xor_sync(0xffffffffu, nn,  2);
        cosv = dot / ((sqrtf(nn) + 1e-6f) * (mnorm + 1e-6f));
    }
    #pragma unroll
    for (int o = 16; o >= 1; o >>= 1)
        cosv = fminf(cosv, __shfl_xor_sync(0xffffffffu, cosv, o));
    if ((tid & 31) == 0) atomicMinFloat(&simv, cosv);
    __syncthreads();
    if (tid == 0) {
        if (isQ) g_qsim[bh][blk] = simv; else g_ksim[bh][blk] = simv;
    }
}

// ---------------------------------------------------------------------------
// Kernel 2b: pooled softmax + CDF keep -> block mask.
// ---------------------------------------------------------------------------
__global__ void __launch_bounds__(256) mask_kernel() {
    int bh = blockIdx.x;
    __shared__ float pooled[NQ][NK];
    __shared__ float qs[NQ], kss[NK];
    int tid = threadIdx.x;
    if (tid < NQ) qs[tid]  = g_qsim[bh][tid];
    if (tid < NK) kss[tid] = g_ksim[bh][tid];
    for (int e = tid; e < NQ * NK; e += 256) {
        int qi = e >> 5, ki = e & 31;
        const float* a = g_qm[bh][qi];
        const float* b = g_km[bh][ki];
        float dot = 0.f;
        #pragma unroll
        for (int d = 0; d < DD; d++) dot += a[d] * b[d];
        pooled[qi][ki] = dot * SCALE;
    }
    __syncthreads();
    if (tid < NQ) {
        float vals[NK]; int idx[NK];
        float mx = -CUDART_INF_F;
        for (int i = 0; i < NK; i++) mx = fmaxf(mx, pooled[tid][i]);
        float sum = 0.f;
        for (int i = 0; i < NK; i++) { vals[i] = expf(pooled[tid][i] - mx); sum += vals[i]; }
        float inv = 1.f / sum;
        for (int i = 0; i < NK; i++) { vals[i] *= inv; idx[i] = i; }
        for (int i = 1; i < NK; i++) {
            float kv = vals[i]; int ki = idx[i];
            int j = i - 1;
            while (j >= 0 && vals[j] < kv) { vals[j+1] = vals[j]; idx[j+1] = idx[j]; j--; }
            vals[j+1] = kv; idx[j+1] = ki;
        }
        unsigned keep = 0u;
        float csum = 0.f;
        for (int i = 0; i < NK; i++) {
            if (csum < CDFTH) keep |= (1u << idx[i]);
            csum += vals[i];
        }
        bool qself = qs[tid] > SIMTH;
        int* mrow = g_mask + (bh * NQ + tid) * NK;
        for (int ki = 0; ki < NK; ki++) {
            bool kself = kss[ki] > SIMTH;
            mrow[ki] = (((keep >> ki) & 1u) || !qself || !kself) ? 1 : 0;
        }
    }
}

// ---------------------------------------------------------------------------
// Kernel 3: block-sparse flash attention, fp16 m16n8k16 mma.
// Q A-frags in regs (32 u32); K/V fp16 paired B-frags double-buffered via
// cp.async (8KB/tile); P roundtrip in fp16 (conflict-free STS.32/LDS.32).
// grid = (16 q-tiles of 128 rows, 16 bh), 128 threads = 4 warps.
// smem: K[2][2048u32] V[2][2048u32] Pp[4w][1024u32] = 48 KB -> 2 CTAs/SM.
// ---------------------------------------------------------------------------
#define ATT_KV_U32 2048
#define ATT_SMEM_U32 (4*ATT_KV_U32 + 4*1024)   // 12288
#define ATT_SMEM_BYTES (ATT_SMEM_U32 * 4)      // 49152

__global__ void __launch_bounds__(128, 2) attn_fp16() {
    const int qb = blockIdx.x;
    const int bh = blockIdx.y;
    const int b = bh >> 3, h = bh & 7;
    const int tid  = threadIdx.x;
    const int wid  = tid >> 5;
    const int lane = tid & 31;
    const int lr = lane >> 2;
    const int lc = lane & 3;

    unsigned* sm_u = (unsigned*)sm_dyn;
    unsigned* Kbuf = sm_u;                           // [2][2048]
    unsigned* Vbuf = sm_u + 2 * ATT_KV_U32;          // [2][2048]
    unsigned* PpW  = Vbuf + 2 * ATT_KV_U32 + wid * 1024; // [8 nt][2 g][2 c2][32]
    unsigned sbase  = (unsigned)__cvta_generic_to_shared(sm_dyn);
    unsigned kbuf_u = sbase;
    unsigned vbuf_u = sbase + 2u * ATT_KV_U32 * 4u;

    __shared__ int s_list[NK];
    __shared__ int s_nk;

    // Q fp16 A-fragments -> registers (2 chunks x 4 ksteps x 4 regs)
    unsigned qh[2][4][4];
    {
        const uint4* qg = (const uint4*)(g_qph + ((size_t)(bh * NQ + qb)) * 4096);
        #pragma unroll
        for (int g = 0; g < 2; g++)
            #pragma unroll
            for (int kk = 0; kk < 4; kk++) {
                uint4 v = qg[((2 * wid + g) * 4 + kk) * 32 + lane];
                qh[g][kk][0] = v.x; qh[g][kk][1] = v.y;
                qh[g][kk][2] = v.z; qh[g][kk][3] = v.w;
            }
    }

    // Kept-block list
    const int* mrow = g_mask + (bh * NQ + qb) * NK;
    if (tid == 0) {
        int c = 0;
        for (int i = 0; i < NK; i++) if (mrow[i]) s_list[c++] = i;
        s_nk = c;
    }
    __syncthreads();
    const int nkeep = s_nk;

    const unsigned* kgp = g_kph + (size_t)bh * NK * 2048;
    const unsigned* vgp = g_vph + (size_t)bh * NK * 2048;

    auto stage_kv = [&](int buf, int kb) {
        const unsigned* ks = kgp + (size_t)kb * 2048;
        const unsigned* vs = vgp + (size_t)kb * 2048;
        unsigned ko = kbuf_u + (unsigned)(buf * ATT_KV_U32) * 4u;
        unsigned vo = vbuf_u + (unsigned)(buf * ATT_KV_U32) * 4u;
        #pragma unroll
        for (int i = 0; i < 4; i++) {        // 512 uint4 each
            unsigned off = (unsigned)(tid + i * 128) * 16u;
            cp16(ko + off, ks + (tid + i * 128) * 4);
            cp16(vo + off, vs + (tid + i * 128) * 4);
        }
        asm volatile("cp.async.commit_group;");
    };

    stage_kv(0, s_list[0]);

    float o[2][8][4];
    #pragma unroll
    for (int g = 0; g < 2; g++)
        #pragma unroll
        for (int nt = 0; nt < 8; nt++)
            #pragma unroll
            for (int j = 0; j < 4; j++) o[g][nt][j] = 0.f;
    float m[4] = {-CUDART_INF_F, -CUDART_INF_F, -CUDART_INF_F, -CUDART_INF_F};
    float l[4] = {0.f, 0.f, 0.f, 0.f};

    for (int i = 0; i < nkeep; i++) {
        int buf = i & 1;
        asm volatile("cp.async.wait_group 0;");
        __syncthreads();
        if (i + 1 < nkeep) stage_kv(buf ^ 1, s_list[i + 1]);

        const uint4* Kp4 = (const uint4*)(Kbuf + buf * ATT_KV_U32);
        const uint4* Vp4 = (const uint4*)(Vbuf + buf * ATT_KV_U32);

        // ---- S = Q K^T : 4 ksteps x 4 ntp, LDS.128 -> 4 mma ----
        float sc[2][8][4];
        #pragma unroll
        for (int g = 0; g < 2; g++)
            #pragma unroll
            for (int nt = 0; nt < 8; nt++)
                #pragma unroll
                for (int j = 0; j < 4; j++) sc[g][nt][j] = 0.f;

        #pragma unroll
        for (int kk = 0; kk < 4; kk++) {
            #pragma unroll
            for (int ntp = 0; ntp < 4; ntp++) {
                uint4 kv = Kp4[kk * 128 + ntp * 32 + lane];
                int nte = 2 * ntp, nto = nte + 1;
                mma_f16(sc[0][nte], qh[0][kk][0], qh[0][kk][1],
                        qh[0][kk][2], qh[0][kk][3], kv.x, kv.y);
                mma_f16(sc[1][nte], qh[1][kk][0], qh[1][kk][1],
                        qh[1][kk][2], qh[1][kk][3], kv.x, kv.y);
                mma_f16(sc[0][nto], qh[0][kk][0], qh[0][kk][1],
                        qh[0][kk][2], qh[0][kk][3], kv.z, kv.w);
                mma_f16(sc[1][nto], qh[1][kk][0], qh[1][kk][1],
                        qh[1][kk][2], qh[1][kk][3], kv.z, kv.w);
            }
        }

        // ---- Online softmax ----
        float r0 = -CUDART_INF_F, r1 = -CUDART_INF_F;
        float r2 = -CUDART_INF_F, r3 = -CUDART_INF_F;
        #pragma unroll
        for (int nt = 0; nt < 8; nt++) {
            r0 = fmaxf(r0, fmaxf(sc[0][nt][0], sc[0][nt][1]));
            r1 = fmaxf(r1, fmaxf(sc[0][nt][2], sc[0][nt][3]));
            r2 = fmaxf(r2, fmaxf(sc[1][nt][0], sc[1][nt][1]));
            r3 = fmaxf(r3, fmaxf(sc[1][nt][2], sc[1][nt][3]));
        }
        r0 = fmaxf(r0, __shfl_xor_sync(0xffffffffu, r0, 1));
        r0 = fmaxf(r0, __shfl_xor_sync(0xffffffffu, r0, 2));
        r1 = fmaxf(r1, __shfl_xor_sync(0xffffffffu, r1, 1));
        r1 = fmaxf(r1, __shfl_xor_sync(0xffffffffu, r1, 2));
        r2 = fmaxf(r2, __shfl_xor_sync(0xffffffffu, r2, 1));
        r2 = fmaxf(r2, __shfl_xor_sync(0xffffffffu, r2, 2));
        r3 = fmaxf(r3, __shfl_xor_sync(0xffffffffu, r3, 1));
        r3 = fmaxf(r3, __shfl_xor_sync(0xffffffffu, r3, 2));
        float mn0 = fmaxf(m[0], r0), mn1 = fmaxf(m[1], r1);
        float mn2 = fmaxf(m[2], r2), mn3 = fmaxf(m[3], r3);
        float c0 = __expf(m[0] - mn0), c1 = __expf(m[1] - mn1);
        float c2 = __expf(m[2] - mn2), c3 = __expf(m[3] - mn3);
        #pragma unroll
        for (int nt = 0; nt < 8; nt++) {
            o[0][nt][0] *= c0; o[0][nt][1] *= c0;
            o[0][nt][2] *= c1; o[0][nt][3] *= c1;
            o[1][nt][0] *= c2; o[1][nt][1] *= c2;
            o[1][nt][2] *= c3; o[1][nt][3] *= c3;
        }

        // ---- exp + P store (fp16, conflict-free STS.32) ----
        float s0 = 0.f, s1 = 0.f, s2 = 0.f, s3 = 0.f;
        #pragma unroll
        for (int nt = 0; nt < 8; nt++) {
            float p00 = __expf(sc[0][nt][0] - mn0);
            float p01 = __expf(sc[0][nt][1] - mn0);
            float p02 = __expf(sc[0][nt][2] - mn1);
            float p03 = __expf(sc[0][nt][3] - mn1);
            float p10 = __expf(sc[1][nt][0] - mn2);
            float p11 = __expf(sc[1][nt][1] - mn2);
            float p12 = __expf(sc[1][nt][2] - mn3);
            float p13 = __expf(sc[1][nt][3] - mn3);
            s0 += p00 + p01; s1 += p02 + p03;
            s2 += p10 + p11; s3 += p12 + p13;
            unsigned* Pb = PpW + nt * 128;
            Pb[lane]       = f2h2(p00, p01);   // g0, rows lr
            Pb[32 + lane]  = f2h2(p02, p03);   // g0, rows lr+8
            Pb[64 + lane]  = f2h2(p10, p11);   // g1, rows lr
            Pb[96 + lane]  = f2h2(p12, p13);   // g1, rows lr+8
        }
        __syncwarp();

        // ---- PV: O += P @ V (fp16 A-frags from Pp, B from Vp4) ----
        #pragma unroll
        for (int kk = 0; kk < 4; kk++) {
            unsigned pa[2][4];
            #pragma unroll
            for (int g = 0; g < 2; g++) {
                pa[g][0] = PpW[(2 * kk    ) * 128 + g * 64 +      lane];
                pa[g][1] = PpW[(2 * kk    ) * 128 + g * 64 + 32 + lane];
                pa[g][2] = PpW[(2 * kk + 1) * 128 + g * 64 +      lane];
                pa[g][3] = PpW[(2 * kk + 1) * 128 + g * 64 + 32 + lane];
            }
            #pragma unroll
            for (int ntp = 0; ntp < 4; ntp++) {
                uint4 vv = Vp4[kk * 128 + ntp * 32 + lane];
                int nte = 2 * ntp, nto = nte + 1;
                mma_f16(o[0][nte], pa[0][0], pa[0][1], pa[0][2], pa[0][3], vv.x, vv.y);
                mma_f16(o[1][nte], pa[1][0], pa[1][1], pa[1][2], pa[1][3], vv.x, vv.y);
                mma_f16(o[0][nto], pa[0][0], pa[0][1], pa[0][2], pa[0][3], vv.z, vv.w);
                mma_f16(o[1][nto], pa[1][0], pa[1][1], pa[1][2], pa[1][3], vv.z, vv.w);
            }
        }
        __syncwarp();    // PV reads done before next iter's P overwrite

        s0 += __shfl_xor_sync(0xffffffffu, s0, 1);
        s0 += __shfl_xor_sync(0xffffffffu, s0, 2);
        s1 += __shfl_xor_sync(0xffffffffu, s1, 1);
        s1 += __shfl_xor_sync(0xffffffffu, s1, 2);
        s2 += __shfl_xor_sync(0xffffffffu, s2, 1);
        s2 += __shfl_xor_sync(0xffffffffu, s2, 2);
        s3 += __shfl_xor_sync(0xffffffffu, s3, 1);
        s3 += __shfl_xor_sync(0xffffffffu, s3, 2);
        l[0] = l[0] * c0 + s0;
        l[1] = l[1] * c1 + s1;
        l[2] = l[2] * c2 + s2;
        l[3] = l[3] * c3 + s3;
        m[0] = mn0; m[1] = mn1; m[2] = mn2; m[3] = mn3;
    }

    // Epilogue: normalize and scatter to g_o
    float inv0 = 1.f / l[0], inv1 = 1.f / l[1];
    float inv2 = 1.f / l[2], inv3 = 1.f / l[3];
    int r0r = qb * 128 + wid * 32 + lr;
    float* og = g_o + (size_t)b * LL * CC + h * DD;
    #pragma unroll
    for (int nt = 0; nt < 8; nt++) {
        float2 w0 = make_float2(o[0][nt][0] * inv0, o[0][nt][1] * inv0);
        float2 w1 = make_float2(o[0][nt][2] * inv1, o[0][nt][3] * inv1);
        float2 w2 = make_float2(o[1][nt][0] * inv2, o[1][nt][1] * inv2);
        float2 w3 = make_float2(o[1][nt][2] * inv3, o[1][nt][3] * inv3);
        *(float2*)&og[(size_t)(r0r     ) * CC + nt * 8 + 2 * lc] = w0;
        *(float2*)&og[(size_t)(r0r +  8) * CC + nt * 8 + 2 * lc] = w1;
        *(float2*)&og[(size_t)(r0r + 16) * CC + nt * 8 + 2 * lc] = w2;
        *(float2*)&og[(size_t)(r0r + 24) * CC + nt * 8 + 2 * lc] = w3;
    }
}

// ---------------------------------------------------------------------------
extern "C" void kernel_launch(void* const* d_in, const int* in_sizes, int n_in,
                              void* d_out, int out_size) {
    const float* x     = (const float*)d_in[0];
    const float* Wqkv  = (const float*)d_in[1];
    const float* bqkv  = (const float*)d_in[2];
    const float* Wproj = (const float*)d_in[3];
    const float* bproj = (const float*)d_in[4];
    float* out = (float*)d_out;

    cudaFuncSetAttribute(attn_fp16, cudaFuncAttributeMaxDynamicSharedMemorySize,
                         ATT_SMEM_BYTES);
    cudaFuncSetAttribute(gemm_tf32<NQKV, true>,
                         cudaFuncAttributeMaxDynamicSharedMemorySize, GEMM_SMEM_BYTES);
    cudaFuncSetAttribute(gemm_tf32<CC, false>,
                         cudaFuncAttributeMaxDynamicSharedMemorySize, GEMM_SMEM_BYTES);

    gemm_tf32<NQKV, true><<<dim3(NQKV / 128, MM / 128), 256, GEMM_SMEM_BYTES>>>(
        x, Wqkv, bqkv, nullptr);
    meansim_kernel<<<dim3(NQ + NK, BB * HH), 256>>>();
    mask_kernel<<<BB * HH, 256>>>();
    attn_fp16<<<dim3(NQ, BB * HH), 128, ATT_SMEM_BYTES>>>();
    gemm_tf32<CC, false><<<dim3(CC / 128, MM / 128), 256, GEMM_SMEM_BYTES>>>(
        nullptr, Wproj, bproj, out);
}